// round 5
// baseline (speedup 1.0000x reference)
#include <cuda_runtime.h>
#include <cuda_bf16.h>
#include <math.h>

// Problem constants
#define BGR   16384
#define NNODE 55
#define NTOT  (BGR * NNODE)        // 901120
#define INCH  13
#define HID   32
#define MQ    6
#define NEDGE (4 * NTOT)           // 3604480
#define NP1   (NTOT + 1)           // 901121
#define NB_SCAN ((NP1 + 1023) / 1024)  // 881

// ---------------- device scratch (no allocations allowed) ----------------
__device__ int   g_cnt[NP1];
__device__ int   g_rowptr[NP1];
__device__ int   g_cursor[NTOT];
__device__ int   g_bsum[1024];
__device__ int   g_srcs[NEDGE];
__device__ float g_hA[(size_t)NTOT * HID];
__device__ float g_hB[(size_t)NTOT * HID];
__device__ float g_jk[(size_t)NTOT * HID];

__device__ __forceinline__ float selu_f(float v) {
    const float sc = 1.0507009873554804934193349852946f;
    const float al = 1.6732632423543772848170429916717f;
    return v > 0.0f ? sc * v : sc * al * expm1f(v);
}

// ---------------- CSR build ----------------
__global__ void k_zero() {
    int i = blockIdx.x * blockDim.x + threadIdx.x;
    if (i < NP1) g_cnt[i] = 0;
}

__global__ void k_count(const int* __restrict__ ei) {
    int i = blockIdx.x * blockDim.x + threadIdx.x;
    if (i < NEDGE) {
        unsigned d = (unsigned)ei[NEDGE + i];
        if (d < NTOT) atomicAdd(&g_cnt[d], 1);
    }
}

__global__ void k_scan1() {
    __shared__ int s[1024];
    int t = threadIdx.x;
    int i = blockIdx.x * 1024 + t;
    int v = (i < NP1) ? g_cnt[i] : 0;
    s[t] = v;
    for (int off = 1; off < 1024; off <<= 1) {
        __syncthreads();
        int xx = (t >= off) ? s[t - off] : 0;
        __syncthreads();
        s[t] += xx;
    }
    __syncthreads();
    int excl = (t == 0) ? 0 : s[t - 1];
    if (i < NP1) g_rowptr[i] = excl;
    if (t == 1023) g_bsum[blockIdx.x] = s[1023];
}

__global__ void k_scan2() {
    __shared__ int s[1024];
    int t = threadIdx.x;
    int v = (t < NB_SCAN) ? g_bsum[t] : 0;
    s[t] = v;
    for (int off = 1; off < 1024; off <<= 1) {
        __syncthreads();
        int xx = (t >= off) ? s[t - off] : 0;
        __syncthreads();
        s[t] += xx;
    }
    __syncthreads();
    int excl = (t == 0) ? 0 : s[t - 1];
    g_bsum[t] = excl;
}

__global__ void k_scan3() {
    int t = threadIdx.x;
    int i = blockIdx.x * 1024 + t;
    if (i < NP1) {
        int v = g_rowptr[i] + g_bsum[blockIdx.x];
        g_rowptr[i] = v;
        if (i < NTOT) g_cursor[i] = v;
    }
}

__global__ void k_reorder(const int* __restrict__ ei) {
    int i = blockIdx.x * blockDim.x + threadIdx.x;
    if (i < NEDGE) {
        unsigned s = (unsigned)ei[i];
        unsigned d = (unsigned)ei[NEDGE + i];
        if (d < NTOT && s < NTOT) {
            int pos = atomicAdd(&g_cursor[d], 1);
            g_srcs[pos] = (int)s;
        }
    }
}

// ---------------- SAGE layer 0 (13 -> 32) ----------------
__global__ void __launch_bounds__(128) k_layer0(
    const float* __restrict__ x,
    const float* __restrict__ wl0, const float* __restrict__ bl0,
    const float* __restrict__ wr0)
{
    int lane = threadIdx.x & 31;
    int warp = (blockIdx.x * blockDim.x + threadIdx.x) >> 5;
    int nw = (gridDim.x * blockDim.x) >> 5;

    float wlc[INCH], wrc[INCH];
#pragma unroll
    for (int k = 0; k < INCH; k++) {
        wlc[k] = wl0[k * HID + lane];
        wrc[k] = wr0[k * HID + lane];
    }
    float bias = bl0[lane];

    for (int node = warp; node < NTOT; node += nw) {
        int s = g_rowptr[node], e = g_rowptr[node + 1];
        float acc = 0.0f;
        if (lane < INCH) {
            for (int j = s; j < e; j++) {
                int sr = g_srcs[j];
                acc += x[sr * INCH + lane];
            }
        }
        float inv = (e > s) ? 1.0f / (float)(e - s) : 0.0f;
        float a = acc * inv;
        float hk = (lane < INCH) ? x[node * INCH + lane] : 0.0f;
        float o = bias;
#pragma unroll
        for (int k = 0; k < INCH; k++) {
            o = fmaf(__shfl_sync(0xffffffffu, a, k), wlc[k], o);
            o = fmaf(__shfl_sync(0xffffffffu, hk, k), wrc[k], o);
        }
        float hn = selu_f(o);
        size_t idx = (size_t)node * HID + lane;
        g_hA[idx] = hn;
        g_jk[idx] = hn;
    }
}

// ---------------- SAGE layers 1..4 (32 -> 32) ----------------
__global__ void __launch_bounds__(128) k_layer(
    int dir,
    const float* __restrict__ wlp, const float* __restrict__ blp,
    const float* __restrict__ wrp)
{
    const float* __restrict__ hin = dir ? g_hB : g_hA;
    float* __restrict__ hout = dir ? g_hA : g_hB;

    int lane = threadIdx.x & 31;
    int warp = (blockIdx.x * blockDim.x + threadIdx.x) >> 5;
    int nw = (gridDim.x * blockDim.x) >> 5;

    float wlc[HID], wrc[HID];
#pragma unroll
    for (int k = 0; k < HID; k++) {
        wlc[k] = wlp[k * HID + lane];
        wrc[k] = wrp[k * HID + lane];
    }
    float bias = blp[lane];

    for (int node = warp; node < NTOT; node += nw) {
        int s = g_rowptr[node], e = g_rowptr[node + 1];
        float acc = 0.0f;
        for (int j = s; j < e; j++) {
            int sr = g_srcs[j];
            acc += hin[(size_t)sr * HID + lane];
        }
        float inv = (e > s) ? 1.0f / (float)(e - s) : 0.0f;
        float a = acc * inv;
        float hk = hin[(size_t)node * HID + lane];
        float o = bias;
#pragma unroll
        for (int k = 0; k < HID; k++) {
            o = fmaf(__shfl_sync(0xffffffffu, a, k), wlc[k], o);
            o = fmaf(__shfl_sync(0xffffffffu, hk, k), wrc[k], o);
        }
        float hn = selu_f(o);
        size_t idx = (size_t)node * HID + lane;
        hout[idx] = hn;
        g_jk[idx] = fmaxf(g_jk[idx], hn);
    }
}

// ---------------- per-graph attention + FC ----------------
__global__ void __launch_bounds__(128) k_attn(
    const float* __restrict__ x,
    const int* __restrict__ shuf,
    const float* __restrict__ wq, const float* __restrict__ bq,
    const float* __restrict__ wk, const float* __restrict__ bk,
    const float* __restrict__ wv, const float* __restrict__ bv,
    const float* __restrict__ wo, const float* __restrict__ bo,
    const float* __restrict__ wfc, const float* __restrict__ bfc,
    float* __restrict__ out)
{
    __shared__ float keys[NNODE * HID];      // 7040 B
    __shared__ float Ks[NNODE * 33];         // padded, 7260 B
    __shared__ float Vs[NNODE * 33];
    __shared__ float wq_s[HID * HID];
    __shared__ float wo_s[HID * HID];
    __shared__ float wfc_s[HID * MQ * MQ];   // 1152 floats
    __shared__ float Qs[MQ * HID];
    __shared__ float sc[MQ * 56];
    __shared__ float ao[MQ * HID];
    __shared__ float s192[MQ * HID];
    __shared__ float msk[NNODE];
    __shared__ float rsum[MQ];
    __shared__ int order[MQ];
    __shared__ int qidx[MQ];

    int g = blockIdx.x;
    int tid = threadIdx.x;
    int lane = tid & 31;
    int w = tid >> 5;
    int nbase = g * NNODE;                   // first node of graph
    size_t jbase = (size_t)nbase * HID;

    // keys = selu(jk)
    for (int i = tid; i < NNODE * HID; i += 128)
        keys[i] = selu_f(g_jk[jbase + i]);
    // small weights to smem
    for (int i = tid; i < HID * HID; i += 128) { wq_s[i] = wq[i]; wo_s[i] = wo[i]; }
    for (int i = tid; i < HID * MQ * MQ; i += 128) wfc_s[i] = wfc[i];
    // neighbor mask (x column 10)
    if (tid < NNODE) msk[tid] = x[(nbase + tid) * INCH + (INCH - 3)];
    __syncthreads();

    if (tid == 0) {
        int c = 0;
        for (int j = 0; j < NNODE; j++)
            if (msk[j] > 0.5f) { if (c < MQ) order[c] = j; c++; }
        // safety fill (exactly MQ ones expected)
        for (; c < MQ; c++) order[c] = 0;
    }
    __syncthreads();
    if (tid < MQ) {
        int si = shuf[g * MQ + tid];
        si = si < 0 ? 0 : (si > MQ - 1 ? MQ - 1 : si);
        qidx[tid] = order[si];
    }

    // K, V : shfl matvec with weight columns in registers
    float wkc[HID], wvc[HID];
#pragma unroll
    for (int k = 0; k < HID; k++) {
        wkc[k] = wk[k * HID + lane];
        wvc[k] = wv[k * HID + lane];
    }
    float bkl = bk[lane], bvl = bv[lane];
    for (int r = w; r < NNODE; r += 4) {
        float kv = keys[r * HID + lane];
        float ok = bkl, ov = bvl;
#pragma unroll
        for (int k = 0; k < HID; k++) {
            float b = __shfl_sync(0xffffffffu, kv, k);
            ok = fmaf(b, wkc[k], ok);
            ov = fmaf(b, wvc[k], ov);
        }
        Ks[r * 33 + lane] = ok;
        Vs[r * 33 + lane] = ov;
    }
    __syncthreads();

    // Q = keys[qidx] @ wq + bq   (6x32 outputs)
    for (int idx = tid; idx < MQ * HID; idx += 128) {
        int q = idx >> 5, c = idx & 31;
        const float* kr = &keys[qidx[q] * HID];
        float o = bq[c];
#pragma unroll
        for (int k = 0; k < HID; k++) o = fmaf(kr[k], wq_s[k * HID + c], o);
        Qs[q * HID + c] = o;
    }
    __syncthreads();

    // scores (6x55) with 1/sqrt(32)
    const float scale = 0.17677669529663687f;
    for (int idx = tid; idx < MQ * NNODE; idx += 128) {
        int q = idx / NNODE, j = idx % NNODE;
        float o = 0.0f;
#pragma unroll
        for (int k = 0; k < HID; k++) o = fmaf(Qs[q * HID + k], Ks[j * 33 + k], o);
        sc[q * 56 + j] = o * scale;
    }
    __syncthreads();

    // softmax rows
    if (tid < MQ) {
        float m = -1e30f;
        for (int j = 0; j < NNODE; j++) m = fmaxf(m, sc[tid * 56 + j]);
        float sum = 0.0f;
        for (int j = 0; j < NNODE; j++) {
            float e = expf(sc[tid * 56 + j] - m);
            sc[tid * 56 + j] = e;
            sum += e;
        }
        rsum[tid] = 1.0f / sum;
    }
    __syncthreads();

    // attn @ V  (6x32)
    for (int idx = tid; idx < MQ * HID; idx += 128) {
        int q = idx >> 5, d = idx & 31;
        float o = 0.0f;
        for (int j = 0; j < NNODE; j++) o = fmaf(sc[q * 56 + j], Vs[j * 33 + d], o);
        ao[q * HID + d] = o * rsum[q];
    }
    __syncthreads();

    // @ wo + bo, selu
    for (int idx = tid; idx < MQ * HID; idx += 128) {
        int q = idx >> 5, d = idx & 31;
        float o = bo[d];
#pragma unroll
        for (int k = 0; k < HID; k++) o = fmaf(ao[q * HID + k], wo_s[k * HID + d], o);
        s192[idx] = selu_f(o);
    }
    __syncthreads();

    // final FC (192 -> 6)
    if (tid < MQ) {
        float o = bfc[tid];
        for (int i = 0; i < MQ * HID; i++) o = fmaf(s192[i], wfc_s[i * MQ + tid], o);
        out[(size_t)g * MQ + tid] = o;
    }
}

// ---------------- host ----------------
extern "C" void kernel_launch(void* const* d_in, const int* in_sizes, int n_in,
                              void* d_out, int out_size) {
    const float* x    = (const float*)d_in[0];
    const int*   ei   = (const int*)d_in[1];     // int32 per harness dtype palette
    const int*   shf  = (const int*)d_in[2];     // int32
    const float* wl0 = (const float*)d_in[3];
    const float* bl0 = (const float*)d_in[4];
    const float* wr0 = (const float*)d_in[5];
    const float* wl  = (const float*)d_in[6];
    const float* bl  = (const float*)d_in[7];
    const float* wr  = (const float*)d_in[8];
    const float* wq  = (const float*)d_in[9];
    const float* bq  = (const float*)d_in[10];
    const float* wk  = (const float*)d_in[11];
    const float* bk  = (const float*)d_in[12];
    const float* wv  = (const float*)d_in[13];
    const float* bv  = (const float*)d_in[14];
    const float* wo  = (const float*)d_in[15];
    const float* bo  = (const float*)d_in[16];
    const float* wfc = (const float*)d_in[17];
    const float* bfc = (const float*)d_in[18];
    float* out = (float*)d_out;

    // CSR build (per launch; edges are an input)
    k_zero   <<<(NP1 + 255) / 256, 256>>>();
    k_count  <<<(NEDGE + 255) / 256, 256>>>(ei);
    k_scan1  <<<NB_SCAN, 1024>>>();
    k_scan2  <<<1, 1024>>>();
    k_scan3  <<<NB_SCAN, 1024>>>();
    k_reorder<<<(NEDGE + 255) / 256, 256>>>(ei);

    // SAGE stack with fused mean-agg + dual matvec + JK max
    k_layer0<<<2368, 128>>>(x, wl0, bl0, wr0);
    for (int i = 0; i < 4; i++)
        k_layer<<<2368, 128>>>(i & 1, wl + i * HID * HID, bl + i * HID, wr + i * HID * HID);

    // per-graph attention + FC
    k_attn<<<BGR, 128>>>(x, shf, wq, bq, wk, bk, wv, bv, wo, bo, wfc, bfc, out);
}

// round 8
// speedup vs baseline: 2.1000x; 2.1000x over previous
#include <cuda_runtime.h>
#include <cuda_bf16.h>
#include <math.h>

// Problem constants
#define BGR   16384
#define NNODE 55
#define NTOT  (BGR * NNODE)        // 901120
#define INCH  13
#define HID   32
#define MQ    6
#define NEDGE (4 * NTOT)           // 3604480
#define NP1   (NTOT + 1)           // 901121
#define NB_SCAN ((NP1 + 1023) / 1024)  // 881

// ---------------- device scratch (no allocations allowed) ----------------
__device__ int   g_cnt[NP1];
__device__ int   g_rowptr[NP1];
__device__ int   g_cursor[NTOT];
__device__ int   g_bsum[1024];
__device__ int   g_srcs[NEDGE];
__device__ __align__(16) float g_hA[(size_t)NTOT * HID];
__device__ __align__(16) float g_hB[(size_t)NTOT * HID];
__device__ __align__(16) float g_jk[(size_t)NTOT * HID];

__device__ __forceinline__ float selu_f(float v) {
    const float sc = 1.0507009873554804934193349852946f;
    const float al = 1.6732632423543772848170429916717f;
    return v > 0.0f ? sc * v : sc * al * expm1f(v);
}

// ---------------- CSR build ----------------
__global__ void k_zero() {
    int i = blockIdx.x * blockDim.x + threadIdx.x;
    if (i < NP1) g_cnt[i] = 0;
}

__global__ void k_count(const int* __restrict__ ei) {
    int i = blockIdx.x * blockDim.x + threadIdx.x;
    if (i < NEDGE) {
        unsigned d = (unsigned)ei[NEDGE + i];
        if (d < NTOT) atomicAdd(&g_cnt[d], 1);
    }
}

__global__ void k_scan1() {
    __shared__ int s[1024];
    int t = threadIdx.x;
    int i = blockIdx.x * 1024 + t;
    int v = (i < NP1) ? g_cnt[i] : 0;
    s[t] = v;
    for (int off = 1; off < 1024; off <<= 1) {
        __syncthreads();
        int xx = (t >= off) ? s[t - off] : 0;
        __syncthreads();
        s[t] += xx;
    }
    __syncthreads();
    int excl = (t == 0) ? 0 : s[t - 1];
    if (i < NP1) g_rowptr[i] = excl;
    if (t == 1023) g_bsum[blockIdx.x] = s[1023];
}

__global__ void k_scan2() {
    __shared__ int s[1024];
    int t = threadIdx.x;
    int v = (t < NB_SCAN) ? g_bsum[t] : 0;
    s[t] = v;
    for (int off = 1; off < 1024; off <<= 1) {
        __syncthreads();
        int xx = (t >= off) ? s[t - off] : 0;
        __syncthreads();
        s[t] += xx;
    }
    __syncthreads();
    int excl = (t == 0) ? 0 : s[t - 1];
    g_bsum[t] = excl;
}

__global__ void k_scan3() {
    int t = threadIdx.x;
    int i = blockIdx.x * 1024 + t;
    if (i < NP1) {
        int v = g_rowptr[i] + g_bsum[blockIdx.x];
        g_rowptr[i] = v;
        if (i < NTOT) g_cursor[i] = v;
    }
}

__global__ void k_reorder(const int* __restrict__ ei) {
    int i = blockIdx.x * blockDim.x + threadIdx.x;
    if (i < NEDGE) {
        unsigned s = (unsigned)ei[i];
        unsigned d = (unsigned)ei[NEDGE + i];
        if (d < NTOT && s < NTOT) {
            int pos = atomicAdd(&g_cursor[d], 1);
            g_srcs[pos] = (int)s;
        }
    }
}

// ---------------- SAGE layer 0 (13 -> 32), 128 nodes/block ----------------
// z = [agg(13) | x_self(13)], W0 = [Wl0 ; Wr0] (26 x 32)
__global__ void __launch_bounds__(256) k_layer0(
    const float* __restrict__ x,
    const float* __restrict__ wl0, const float* __restrict__ bl0,
    const float* __restrict__ wr0)
{
    __shared__ __align__(16) float W0[26 * 32];
    __shared__ __align__(16) float bias[32];
    __shared__ __align__(16) float Z[128 * 27];

    int tid = threadIdx.x;
    int base = blockIdx.x * 128;

    for (int i = tid; i < 26 * 32; i += 256)
        W0[i] = (i < 13 * 32) ? wl0[i] : wr0[i - 13 * 32];
    if (tid < 32) bias[tid] = bl0[tid];

    // gather: half-warp per node (16 lanes, ch = lane&15)
    int lane = tid & 31, wp = tid >> 5;
    int hw = lane >> 4, ln = lane & 15;
    for (int it = 0; it < 8; it++) {
        int n = wp * 16 + it * 2 + hw;
        int node = base + n;
        int s = g_rowptr[node], e = g_rowptr[node + 1];
        float a = 0.0f;
#pragma unroll 4
        for (int j = s; j < e; j++) {
            int sr = g_srcs[j];
            if (ln < INCH) a += x[(size_t)sr * INCH + ln];
        }
        float inv = (e > s) ? 1.0f / (float)(e - s) : 0.0f;
        a *= inv;
        if (ln < INCH) {
            Z[n * 27 + ln] = a;
            Z[n * 27 + INCH + ln] = x[(size_t)node * INCH + ln];
        }
    }
    __syncthreads();

    // epilogue: 2 threads/node, 16 outputs each
    int n = tid >> 1, half = tid & 1, cb = half * 16;
    float acc[16];
#pragma unroll
    for (int c = 0; c < 16; c++) acc[c] = bias[cb + c];
    const float* zr = &Z[n * 27];
#pragma unroll 2
    for (int k = 0; k < 26; k++) {
        float zk = zr[k];
        const float4* w4 = (const float4*)&W0[k * 32 + cb];
#pragma unroll
        for (int u = 0; u < 4; u++) {
            float4 w = w4[u];
            acc[u * 4 + 0] = fmaf(zk, w.x, acc[u * 4 + 0]);
            acc[u * 4 + 1] = fmaf(zk, w.y, acc[u * 4 + 1]);
            acc[u * 4 + 2] = fmaf(zk, w.z, acc[u * 4 + 2]);
            acc[u * 4 + 3] = fmaf(zk, w.w, acc[u * 4 + 3]);
        }
    }
    int node = base + n;
    size_t rb = (size_t)node * 8 + half * 4;   // float4 units
    float4* hA4 = (float4*)g_hA;
    float4* jk4 = (float4*)g_jk;
#pragma unroll
    for (int u = 0; u < 4; u++) {
        float4 v;
        v.x = selu_f(acc[u * 4 + 0]);
        v.y = selu_f(acc[u * 4 + 1]);
        v.z = selu_f(acc[u * 4 + 2]);
        v.w = selu_f(acc[u * 4 + 3]);
        hA4[rb + u] = v;
        jk4[rb + u] = v;
    }
}

// ---------------- SAGE layers 1..4 (32 -> 32), 128 nodes/block ----------------
// z = [agg(32) | h_self(32)], W = [Wl ; Wr] (64 x 32)
__global__ void __launch_bounds__(256) k_layer(
    int dir, int last,
    const float* __restrict__ wlp, const float* __restrict__ blp,
    const float* __restrict__ wrp)
{
    const float* __restrict__ hin = dir ? g_hB : g_hA;
    float* __restrict__ hout = dir ? g_hA : g_hB;

    __shared__ __align__(16) float W[64 * 32];
    __shared__ __align__(16) float bias[32];
    __shared__ __align__(16) float Z[128 * 68];   // stride 68 floats = 272 B (16B multiple)

    int tid = threadIdx.x;
    int base = blockIdx.x * 128;

    for (int i = tid; i < 64 * 32; i += 256)
        W[i] = (i < 32 * 32) ? wlp[i] : wrp[i - 32 * 32];
    if (tid < 32) bias[tid] = blp[tid];

    // self rows -> Z[:, 32:64] (fully coalesced float4)
    const float4* hin4b = (const float4*)(hin + (size_t)base * HID);
    for (int idx = tid; idx < 128 * 8; idx += 256) {
        float4 v = hin4b[idx];
        int n = idx >> 3, c4 = (idx & 7) << 2;
        *(float4*)&Z[n * 68 + 32 + c4] = v;
    }

    // gather: quarter-warp per node (8 lanes x float4 = 128B row), 4 chains/warp
    int lane = tid & 31, wp = tid >> 5;
    int q = lane >> 3, li = lane & 7;
    const float4* hall4 = (const float4*)hin;
    for (int it = 0; it < 4; it++) {
        int n = wp * 16 + it * 4 + q;
        int node = base + n;
        int s = g_rowptr[node], e = g_rowptr[node + 1];
        float4 acc = make_float4(0.f, 0.f, 0.f, 0.f);
#pragma unroll 4
        for (int j = s; j < e; j++) {
            int sr = g_srcs[j];
            float4 v = hall4[(size_t)sr * 8 + li];
            acc.x += v.x; acc.y += v.y; acc.z += v.z; acc.w += v.w;
        }
        float inv = (e > s) ? 1.0f / (float)(e - s) : 0.0f;
        acc.x *= inv; acc.y *= inv; acc.z *= inv; acc.w *= inv;
        *(float4*)&Z[n * 68 + li * 4] = acc;
    }
    __syncthreads();

    // epilogue: 2 threads/node, 16 outputs each (no shuffles!)
    int n = tid >> 1, half = tid & 1, cb = half * 16;
    float acc[16];
#pragma unroll
    for (int c = 0; c < 16; c++) acc[c] = bias[cb + c];
    const float* zr = &Z[n * 68];
#pragma unroll 8
    for (int k = 0; k < 64; k++) {
        float zk = zr[k];
        const float4* w4 = (const float4*)&W[k * 32 + cb];
#pragma unroll
        for (int u = 0; u < 4; u++) {
            float4 w = w4[u];
            acc[u * 4 + 0] = fmaf(zk, w.x, acc[u * 4 + 0]);
            acc[u * 4 + 1] = fmaf(zk, w.y, acc[u * 4 + 1]);
            acc[u * 4 + 2] = fmaf(zk, w.z, acc[u * 4 + 2]);
            acc[u * 4 + 3] = fmaf(zk, w.w, acc[u * 4 + 3]);
        }
    }
    int node = base + n;
    size_t rb = (size_t)node * 8 + half * 4;
    float4* hout4 = (float4*)hout;
    float4* jk4 = (float4*)g_jk;
#pragma unroll
    for (int u = 0; u < 4; u++) {
        float4 v;
        v.x = selu_f(acc[u * 4 + 0]);
        v.y = selu_f(acc[u * 4 + 1]);
        v.z = selu_f(acc[u * 4 + 2]);
        v.w = selu_f(acc[u * 4 + 3]);
        float4 jv = jk4[rb + u];
        jv.x = fmaxf(jv.x, v.x);
        jv.y = fmaxf(jv.y, v.y);
        jv.z = fmaxf(jv.z, v.z);
        jv.w = fmaxf(jv.w, v.w);
        jk4[rb + u] = jv;
        if (!last) hout4[rb + u] = v;
    }
}

// ---------------- per-graph attention + FC (192 threads = 6 warps) ----------------
__global__ void __launch_bounds__(192) k_attn(
    const float* __restrict__ x,
    const int* __restrict__ shuf,
    const float* __restrict__ wq, const float* __restrict__ bq,
    const float* __restrict__ wk, const float* __restrict__ bk,
    const float* __restrict__ wv, const float* __restrict__ bv,
    const float* __restrict__ wo, const float* __restrict__ bo,
    const float* __restrict__ wfc, const float* __restrict__ bfc,
    float* __restrict__ out)
{
    __shared__ __align__(16) float keys[NNODE * 33];
    __shared__ __align__(16) float KV[NNODE * 68];  // cols 0..31 = K, 32..63 = V
    __shared__ __align__(16) float Wkv[32 * 64];    // [k][c]: c<32 -> wk, else wv
    __shared__ __align__(16) float bkv[64];
    __shared__ __align__(16) float Qs[MQ * 32];
    __shared__ __align__(16) float sc[MQ * 56];
    __shared__ __align__(16) float ao[MQ * 32];
    __shared__ __align__(16) float s192[192];
    __shared__ unsigned mbits[2];
    __shared__ int qidx[MQ];

    int g = blockIdx.x;
    int tid = threadIdx.x;
    int nbase = g * NNODE;

    // keys = selu(jk)
    for (int idx = tid; idx < NNODE * 32; idx += 192) {
        int j = idx >> 5, c = idx & 31;
        keys[j * 33 + c] = selu_f(g_jk[(size_t)nbase * 32 + idx]);
    }
    for (int i = tid; i < 2048; i += 192) {
        int k = i >> 6, c = i & 63;
        Wkv[i] = (c < 32) ? wk[k * 32 + c] : wv[k * 32 + (c - 32)];
    }
    if (tid < 64) bkv[tid] = (tid < 32) ? bk[tid] : bv[tid - 32];

    // neighbor mask bits (warps 0 and 1 only, full warps so ballot is safe)
    if (tid < 64) {
        bool on = (tid < NNODE) ? (x[(size_t)(nbase + tid) * INCH + (INCH - 3)] > 0.5f) : false;
        unsigned b = __ballot_sync(0xffffffffu, on);
        if ((tid & 31) == 0) mbits[tid >> 5] = b;
    }
    __syncthreads();

    if (tid < MQ) {
        int si = shuf[(size_t)g * MQ + tid];
        si = si < 0 ? 0 : (si > MQ - 1 ? MQ - 1 : si);
        unsigned m0 = mbits[0], m1 = mbits[1];
        int c0 = __popc(m0);
        int nth = si, pos = 0;
        unsigned m = m0; int off = 0;
        if (nth >= c0) { nth -= c0; m = m1; off = 32; }
        for (int b = 0; b < 32; b++) {
            if ((m >> b) & 1u) { if (nth == 0) { pos = off + b; break; } nth--; }
        }
        qidx[tid] = pos;
    }
    __syncthreads();

    // Q: thread (q, c), weights from global (L1-cached)
    {
        int q = tid >> 5, c = tid & 31;
        const float* kr = &keys[qidx[q] * 33];
        float o = bq[c];
#pragma unroll 8
        for (int k = 0; k < 32; k++) o = fmaf(kr[k], wq[k * 32 + c], o);
        Qs[tid] = o;
    }

    // K|V mini-GEMM: 55 rows x 64 outputs, 8 outputs/thread
    for (int idx = tid; idx < NNODE * 8; idx += 192) {
        int j = idx >> 3, og = idx & 7, cb = og * 8;
        float a[8];
#pragma unroll
        for (int u = 0; u < 8; u++) a[u] = bkv[cb + u];
        const float* zr = &keys[j * 33];
#pragma unroll 8
        for (int k = 0; k < 32; k++) {
            float zk = zr[k];
            float4 w0 = *(const float4*)&Wkv[k * 64 + cb];
            float4 w1 = *(const float4*)&Wkv[k * 64 + cb + 4];
            a[0] = fmaf(zk, w0.x, a[0]); a[1] = fmaf(zk, w0.y, a[1]);
            a[2] = fmaf(zk, w0.z, a[2]); a[3] = fmaf(zk, w0.w, a[3]);
            a[4] = fmaf(zk, w1.x, a[4]); a[5] = fmaf(zk, w1.y, a[5]);
            a[6] = fmaf(zk, w1.z, a[6]); a[7] = fmaf(zk, w1.w, a[7]);
        }
        *(float4*)&KV[j * 68 + cb] = make_float4(a[0], a[1], a[2], a[3]);
        *(float4*)&KV[j * 68 + cb + 4] = make_float4(a[4], a[5], a[6], a[7]);
    }
    __syncthreads();

    // scores (6 x 55), scaled
    const float scale = 0.17677669529663687f;
    for (int idx = tid; idx < MQ * NNODE; idx += 192) {
        int q = idx / NNODE, j = idx - q * NNODE;
        float o = 0.0f;
#pragma unroll 8
        for (int k = 0; k < 32; k++) o = fmaf(Qs[q * 32 + k], KV[j * 68 + k], o);
        sc[q * 56 + j] = o * scale;
    }
    __syncthreads();

    // softmax: warp q handles row q (normalize in place)
    {
        int q = tid >> 5, lane = tid & 31;
        float v0 = sc[q * 56 + lane];
        float v1 = (lane + 32 < NNODE) ? sc[q * 56 + lane + 32] : -1e30f;
        float m = fmaxf(v0, v1);
#pragma unroll
        for (int o = 16; o > 0; o >>= 1) m = fmaxf(m, __shfl_xor_sync(0xffffffffu, m, o));
        float e0 = expf(v0 - m);
        float e1 = (lane + 32 < NNODE) ? expf(v1 - m) : 0.0f;
        float ssum = e0 + e1;
#pragma unroll
        for (int o = 16; o > 0; o >>= 1) ssum += __shfl_xor_sync(0xffffffffu, ssum, o);
        float rinv = 1.0f / ssum;
        sc[q * 56 + lane] = e0 * rinv;
        if (lane + 32 < NNODE) sc[q * 56 + lane + 32] = e1 * rinv;
    }
    __syncthreads();

    // attn @ V : thread (q, d)
    {
        int q = tid >> 5, d = tid & 31;
        float o = 0.0f;
#pragma unroll 5
        for (int j = 0; j < NNODE; j++) o = fmaf(sc[q * 56 + j], KV[j * 68 + 32 + d], o);
        ao[tid] = o;
    }
    __syncthreads();

    // @ wo + bo, selu
    {
        int q = tid >> 5, d = tid & 31;
        float o = bo[d];
#pragma unroll 8
        for (int k = 0; k < 32; k++) o = fmaf(ao[q * 32 + k], wo[k * 32 + d], o);
        s192[tid] = selu_f(o);
    }
    __syncthreads();

    // final FC (192 -> 6): warp q computes output q
    {
        int q = tid >> 5, lane = tid & 31;
        float o = 0.0f;
#pragma unroll
        for (int i = lane; i < 192; i += 32) o = fmaf(s192[i], wfc[i * MQ + q], o);
#pragma unroll
        for (int off = 16; off > 0; off >>= 1) o += __shfl_xor_sync(0xffffffffu, o, off);
        if (lane == 0) out[(size_t)g * MQ + q] = o + bfc[q];
    }
}

// ---------------- host ----------------
extern "C" void kernel_launch(void* const* d_in, const int* in_sizes, int n_in,
                              void* d_out, int out_size) {
    const float* x    = (const float*)d_in[0];
    const int*   ei   = (const int*)d_in[1];
    const int*   shf  = (const int*)d_in[2];
    const float* wl0 = (const float*)d_in[3];
    const float* bl0 = (const float*)d_in[4];
    const float* wr0 = (const float*)d_in[5];
    const float* wl  = (const float*)d_in[6];
    const float* bl  = (const float*)d_in[7];
    const float* wr  = (const float*)d_in[8];
    const float* wq  = (const float*)d_in[9];
    const float* bq  = (const float*)d_in[10];
    const float* wk  = (const float*)d_in[11];
    const float* bk  = (const float*)d_in[12];
    const float* wv  = (const float*)d_in[13];
    const float* bv  = (const float*)d_in[14];
    const float* wo  = (const float*)d_in[15];
    const float* bo  = (const float*)d_in[16];
    const float* wfc = (const float*)d_in[17];
    const float* bfc = (const float*)d_in[18];
    float* out = (float*)d_out;

    // CSR build
    k_zero   <<<(NP1 + 255) / 256, 256>>>();
    k_count  <<<(NEDGE + 255) / 256, 256>>>(ei);
    k_scan1  <<<NB_SCAN, 1024>>>();
    k_scan2  <<<1, 1024>>>();
    k_scan3  <<<NB_SCAN, 1024>>>();
    k_reorder<<<(NEDGE + 255) / 256, 256>>>(ei);

    const int NBLK = NTOT / 128;   // 7040
    k_layer0<<<NBLK, 256>>>(x, wl0, bl0, wr0);
    for (int i = 0; i < 4; i++)
        k_layer<<<NBLK, 256>>>(i & 1, (i == 3) ? 1 : 0,
                               wl + i * HID * HID, bl + i * HID, wr + i * HID * HID);

    k_attn<<<BGR, 192>>>(x, shf, wq, bq, wk, bk, wv, bv, wo, bo, wfc, bfc, out);
}

// round 9
// speedup vs baseline: 2.2369x; 1.0652x over previous
#include <cuda_runtime.h>
#include <cuda_fp16.h>
#include <math.h>

// Problem constants
#define BGR   16384
#define NNODE 55
#define NTOT  (BGR * NNODE)        // 901120
#define INCH  13
#define HID   32
#define MQ    6
#define NEDGE (4 * NTOT)           // 3604480
#define NP1   (NTOT + 1)           // 901121
#define NB_SCAN ((NP1 + 1023) / 1024)  // 881

// ---------------- device scratch (no allocations allowed) ----------------
__device__ int   g_cnt[NP1];
__device__ int   g_rowptr[NP1];
__device__ int   g_cursor[NTOT];
__device__ int   g_bsum[1024];
__device__ int   g_srcs[NEDGE];
__device__ __align__(16) __half g_hA[(size_t)NTOT * HID];   // fp16 storage, fp32 compute
__device__ __align__(16) __half g_hB[(size_t)NTOT * HID];
__device__ __align__(16) float  g_jk[(size_t)NTOT * HID];   // fp32 (feeds attention)

__device__ __forceinline__ float selu_f(float v) {
    const float sc = 1.0507009873554804934193349852946f;
    const float al = 1.6732632423543772848170429916717f;
    return v > 0.0f ? sc * v : sc * al * expm1f(v);
}

// ---------------- CSR build ----------------
__global__ void k_zero() {
    int i = blockIdx.x * blockDim.x + threadIdx.x;
    if (i < NP1) g_cnt[i] = 0;
}

__global__ void k_count(const int* __restrict__ ei) {
    int i = blockIdx.x * blockDim.x + threadIdx.x;
    if (i < NEDGE) {
        unsigned d = (unsigned)ei[NEDGE + i];
        if (d < NTOT) atomicAdd(&g_cnt[d], 1);
    }
}

__global__ void k_scan1() {
    __shared__ int s[1024];
    int t = threadIdx.x;
    int i = blockIdx.x * 1024 + t;
    int v = (i < NP1) ? g_cnt[i] : 0;
    s[t] = v;
    for (int off = 1; off < 1024; off <<= 1) {
        __syncthreads();
        int xx = (t >= off) ? s[t - off] : 0;
        __syncthreads();
        s[t] += xx;
    }
    __syncthreads();
    int excl = (t == 0) ? 0 : s[t - 1];
    if (i < NP1) g_rowptr[i] = excl;
    if (t == 1023) g_bsum[blockIdx.x] = s[1023];
}

__global__ void k_scan2() {
    __shared__ int s[1024];
    int t = threadIdx.x;
    int v = (t < NB_SCAN) ? g_bsum[t] : 0;
    s[t] = v;
    for (int off = 1; off < 1024; off <<= 1) {
        __syncthreads();
        int xx = (t >= off) ? s[t - off] : 0;
        __syncthreads();
        s[t] += xx;
    }
    __syncthreads();
    int excl = (t == 0) ? 0 : s[t - 1];
    g_bsum[t] = excl;
}

__global__ void k_scan3() {
    int t = threadIdx.x;
    int i = blockIdx.x * 1024 + t;
    if (i < NP1) {
        int v = g_rowptr[i] + g_bsum[blockIdx.x];
        g_rowptr[i] = v;
        if (i < NTOT) g_cursor[i] = v;
    }
}

__global__ void k_reorder(const int* __restrict__ ei) {
    int i = blockIdx.x * blockDim.x + threadIdx.x;
    if (i < NEDGE) {
        unsigned s = (unsigned)ei[i];
        unsigned d = (unsigned)ei[NEDGE + i];
        if (d < NTOT && s < NTOT) {
            int pos = atomicAdd(&g_cursor[d], 1);
            g_srcs[pos] = (int)s;
        }
    }
}

// pack 16 fp32 (after selu) into 16 fp16 and store as 2x uint4 (32B)
__device__ __forceinline__ void store_half16(__half* hp, const float* sv) {
    __half2 t[8];
#pragma unroll
    for (int u = 0; u < 8; u++)
        t[u] = __float22half2_rn(make_float2(sv[2 * u], sv[2 * u + 1]));
    uint4 a, b;
    a.x = *(unsigned*)&t[0]; a.y = *(unsigned*)&t[1];
    a.z = *(unsigned*)&t[2]; a.w = *(unsigned*)&t[3];
    b.x = *(unsigned*)&t[4]; b.y = *(unsigned*)&t[5];
    b.z = *(unsigned*)&t[6]; b.w = *(unsigned*)&t[7];
    ((uint4*)hp)[0] = a;
    ((uint4*)hp)[1] = b;
}

// ---------------- SAGE layer 0 (13 -> 32), 128 nodes/block ----------------
__global__ void __launch_bounds__(256) k_layer0(
    const float* __restrict__ x,
    const float* __restrict__ wl0, const float* __restrict__ bl0,
    const float* __restrict__ wr0)
{
    __shared__ __align__(16) float W0[26 * 32];
    __shared__ __align__(16) float bias[32];
    __shared__ __align__(16) float Z[128 * 27];

    int tid = threadIdx.x;
    int base = blockIdx.x * 128;

    for (int i = tid; i < 26 * 32; i += 256)
        W0[i] = (i < 13 * 32) ? wl0[i] : wr0[i - 13 * 32];
    if (tid < 32) bias[tid] = bl0[tid];

    // gather: half-warp per node
    int lane = tid & 31, wp = tid >> 5;
    int hw = lane >> 4, ln = lane & 15;
    for (int it = 0; it < 8; it++) {
        int n = wp * 16 + it * 2 + hw;
        int node = base + n;
        int s = g_rowptr[node], e = g_rowptr[node + 1];
        float a = 0.0f;
#pragma unroll 4
        for (int j = s; j < e; j++) {
            int sr = g_srcs[j];
            if (ln < INCH) a += x[(size_t)sr * INCH + ln];
        }
        float inv = (e > s) ? 1.0f / (float)(e - s) : 0.0f;
        a *= inv;
        if (ln < INCH) {
            Z[n * 27 + ln] = a;
            Z[n * 27 + INCH + ln] = x[(size_t)node * INCH + ln];
        }
    }
    __syncthreads();

    // epilogue: 2 threads/node, 16 outputs each
    int n = tid >> 1, half = tid & 1, cb = half * 16;
    float acc[16];
#pragma unroll
    for (int c = 0; c < 16; c++) acc[c] = bias[cb + c];
    const float* zr = &Z[n * 27];
#pragma unroll 2
    for (int k = 0; k < 26; k++) {
        float zk = zr[k];
        const float4* w4 = (const float4*)&W0[k * 32 + cb];
#pragma unroll
        for (int u = 0; u < 4; u++) {
            float4 w = w4[u];
            acc[u * 4 + 0] = fmaf(zk, w.x, acc[u * 4 + 0]);
            acc[u * 4 + 1] = fmaf(zk, w.y, acc[u * 4 + 1]);
            acc[u * 4 + 2] = fmaf(zk, w.z, acc[u * 4 + 2]);
            acc[u * 4 + 3] = fmaf(zk, w.w, acc[u * 4 + 3]);
        }
    }
    int node = base + n;
    float sv[16];
#pragma unroll
    for (int c = 0; c < 16; c++) sv[c] = selu_f(acc[c]);
    // jk fp32
    float4* jk4 = (float4*)g_jk;
    size_t rb = (size_t)node * 8 + half * 4;
#pragma unroll
    for (int u = 0; u < 4; u++)
        jk4[rb + u] = make_float4(sv[u * 4], sv[u * 4 + 1], sv[u * 4 + 2], sv[u * 4 + 3]);
    // h fp16
    store_half16(g_hA + (size_t)node * 32 + cb, sv);
}

// ---------------- SAGE layers 1..4 (32 -> 32), 128 nodes/block ----------------
__global__ void __launch_bounds__(256) k_layer(
    int dir, int last,
    const float* __restrict__ wlp, const float* __restrict__ blp,
    const float* __restrict__ wrp)
{
    const __half* __restrict__ hin = dir ? g_hB : g_hA;
    __half* __restrict__ hout = dir ? g_hA : g_hB;

    __shared__ __align__(16) float W[64 * 32];
    __shared__ __align__(16) float bias[32];
    __shared__ __align__(16) float Z[128 * 68];

    int tid = threadIdx.x;
    int base = blockIdx.x * 128;

    for (int i = tid; i < 64 * 32; i += 256)
        W[i] = (i < 32 * 32) ? wlp[i] : wrp[i - 32 * 32];
    if (tid < 32) bias[tid] = blp[tid];

    const uint2* __restrict__ hu = (const uint2*)hin;  // 1 uint2 = 4 halves

    // self rows -> Z[:, 32:64]
    for (int idx = tid; idx < 128 * 8; idx += 256) {
        uint2 v = hu[(size_t)base * 8 + idx];
        __half2 h0 = *(__half2*)&v.x;
        __half2 h1 = *(__half2*)&v.y;
        float2 f0 = __half22float2(h0), f1 = __half22float2(h1);
        int n = idx >> 3, c4 = (idx & 7) << 2;
        *(float4*)&Z[n * 68 + 32 + c4] = make_float4(f0.x, f0.y, f1.x, f1.y);
    }

    // gather: quarter-warp per node (8 lanes x 8B = 64B row), 4 chains/warp
    int lane = tid & 31, wp = tid >> 5;
    int q = lane >> 3, li = lane & 7;
    for (int it = 0; it < 4; it++) {
        int n = wp * 16 + it * 4 + q;
        int node = base + n;
        int s = g_rowptr[node], e = g_rowptr[node + 1];
        float4 acc = make_float4(0.f, 0.f, 0.f, 0.f);
#pragma unroll 4
        for (int j = s; j < e; j++) {
            int sr = g_srcs[j];
            uint2 v = hu[(size_t)sr * 8 + li];
            __half2 h0 = *(__half2*)&v.x;
            __half2 h1 = *(__half2*)&v.y;
            float2 f0 = __half22float2(h0), f1 = __half22float2(h1);
            acc.x += f0.x; acc.y += f0.y; acc.z += f1.x; acc.w += f1.y;
        }
        float inv = (e > s) ? 1.0f / (float)(e - s) : 0.0f;
        acc.x *= inv; acc.y *= inv; acc.z *= inv; acc.w *= inv;
        *(float4*)&Z[n * 68 + li * 4] = acc;
    }
    __syncthreads();

    // epilogue: 2 threads/node, 16 outputs each
    int n = tid >> 1, half = tid & 1, cb = half * 16;
    float acc[16];
#pragma unroll
    for (int c = 0; c < 16; c++) acc[c] = bias[cb + c];
    const float* zr = &Z[n * 68];
#pragma unroll 8
    for (int k = 0; k < 64; k++) {
        float zk = zr[k];
        const float4* w4 = (const float4*)&W[k * 32 + cb];
#pragma unroll
        for (int u = 0; u < 4; u++) {
            float4 w = w4[u];
            acc[u * 4 + 0] = fmaf(zk, w.x, acc[u * 4 + 0]);
            acc[u * 4 + 1] = fmaf(zk, w.y, acc[u * 4 + 1]);
            acc[u * 4 + 2] = fmaf(zk, w.z, acc[u * 4 + 2]);
            acc[u * 4 + 3] = fmaf(zk, w.w, acc[u * 4 + 3]);
        }
    }
    int node = base + n;
    float sv[16];
#pragma unroll
    for (int c = 0; c < 16; c++) sv[c] = selu_f(acc[c]);
    // jk fp32 RMW
    float4* jk4 = (float4*)g_jk;
    size_t rb = (size_t)node * 8 + half * 4;
#pragma unroll
    for (int u = 0; u < 4; u++) {
        float4 jv = jk4[rb + u];
        jv.x = fmaxf(jv.x, sv[u * 4 + 0]);
        jv.y = fmaxf(jv.y, sv[u * 4 + 1]);
        jv.z = fmaxf(jv.z, sv[u * 4 + 2]);
        jv.w = fmaxf(jv.w, sv[u * 4 + 3]);
        jk4[rb + u] = jv;
    }
    if (!last) store_half16(hout + (size_t)node * 32 + cb, sv);
}

// ---------------- per-graph attention + FC (192 threads = 6 warps) ----------------
__global__ void __launch_bounds__(192) k_attn(
    const float* __restrict__ x,
    const int* __restrict__ shuf,
    const float* __restrict__ wq, const float* __restrict__ bq,
    const float* __restrict__ wk, const float* __restrict__ bk,
    const float* __restrict__ wv, const float* __restrict__ bv,
    const float* __restrict__ wo, const float* __restrict__ bo,
    const float* __restrict__ wfc, const float* __restrict__ bfc,
    float* __restrict__ out)
{
    __shared__ __align__(16) float keys[NNODE * 33];
    __shared__ __align__(16) float KV[NNODE * 68];
    __shared__ __align__(16) float Wkv[32 * 64];
    __shared__ __align__(16) float bkv[64];
    __shared__ __align__(16) float Qs[MQ * 32];
    __shared__ __align__(16) float sc[MQ * 56];
    __shared__ __align__(16) float ao[MQ * 32];
    __shared__ __align__(16) float s192[192];
    __shared__ unsigned mbits[2];
    __shared__ int qidx[MQ];

    int g = blockIdx.x;
    int tid = threadIdx.x;
    int nbase = g * NNODE;

    for (int idx = tid; idx < NNODE * 32; idx += 192) {
        int j = idx >> 5, c = idx & 31;
        keys[j * 33 + c] = selu_f(g_jk[(size_t)nbase * 32 + idx]);
    }
    for (int i = tid; i < 2048; i += 192) {
        int k = i >> 6, c = i & 63;
        Wkv[i] = (c < 32) ? wk[k * 32 + c] : wv[k * 32 + (c - 32)];
    }
    if (tid < 64) bkv[tid] = (tid < 32) ? bk[tid] : bv[tid - 32];

    if (tid < 64) {
        bool on = (tid < NNODE) ? (x[(size_t)(nbase + tid) * INCH + (INCH - 3)] > 0.5f) : false;
        unsigned b = __ballot_sync(0xffffffffu, on);
        if ((tid & 31) == 0) mbits[tid >> 5] = b;
    }
    __syncthreads();

    if (tid < MQ) {
        int si = shuf[(size_t)g * MQ + tid];
        si = si < 0 ? 0 : (si > MQ - 1 ? MQ - 1 : si);
        unsigned m0 = mbits[0], m1 = mbits[1];
        int c0 = __popc(m0);
        int nth = si, pos = 0;
        unsigned m = m0; int off = 0;
        if (nth >= c0) { nth -= c0; m = m1; off = 32; }
        for (int b = 0; b < 32; b++) {
            if ((m >> b) & 1u) { if (nth == 0) { pos = off + b; break; } nth--; }
        }
        qidx[tid] = pos;
    }
    __syncthreads();

    {
        int q = tid >> 5, c = tid & 31;
        const float* kr = &keys[qidx[q] * 33];
        float o = bq[c];
#pragma unroll 8
        for (int k = 0; k < 32; k++) o = fmaf(kr[k], wq[k * 32 + c], o);
        Qs[tid] = o;
    }

    for (int idx = tid; idx < NNODE * 8; idx += 192) {
        int j = idx >> 3, og = idx & 7, cb = og * 8;
        float a[8];
#pragma unroll
        for (int u = 0; u < 8; u++) a[u] = bkv[cb + u];
        const float* zr = &keys[j * 33];
#pragma unroll 8
        for (int k = 0; k < 32; k++) {
            float zk = zr[k];
            float4 w0 = *(const float4*)&Wkv[k * 64 + cb];
            float4 w1 = *(const float4*)&Wkv[k * 64 + cb + 4];
            a[0] = fmaf(zk, w0.x, a[0]); a[1] = fmaf(zk, w0.y, a[1]);
            a[2] = fmaf(zk, w0.z, a[2]); a[3] = fmaf(zk, w0.w, a[3]);
            a[4] = fmaf(zk, w1.x, a[4]); a[5] = fmaf(zk, w1.y, a[5]);
            a[6] = fmaf(zk, w1.z, a[6]); a[7] = fmaf(zk, w1.w, a[7]);
        }
        *(float4*)&KV[j * 68 + cb] = make_float4(a[0], a[1], a[2], a[3]);
        *(float4*)&KV[j * 68 + cb + 4] = make_float4(a[4], a[5], a[6], a[7]);
    }
    __syncthreads();

    const float scale = 0.17677669529663687f;
    for (int idx = tid; idx < MQ * NNODE; idx += 192) {
        int q = idx / NNODE, j = idx - q * NNODE;
        float o = 0.0f;
#pragma unroll 8
        for (int k = 0; k < 32; k++) o = fmaf(Qs[q * 32 + k], KV[j * 68 + k], o);
        sc[q * 56 + j] = o * scale;
    }
    __syncthreads();

    {
        int q = tid >> 5, lane = tid & 31;
        float v0 = sc[q * 56 + lane];
        float v1 = (lane + 32 < NNODE) ? sc[q * 56 + lane + 32] : -1e30f;
        float m = fmaxf(v0, v1);
#pragma unroll
        for (int o = 16; o > 0; o >>= 1) m = fmaxf(m, __shfl_xor_sync(0xffffffffu, m, o));
        float e0 = expf(v0 - m);
        float e1 = (lane + 32 < NNODE) ? expf(v1 - m) : 0.0f;
        float ssum = e0 + e1;
#pragma unroll
        for (int o = 16; o > 0; o >>= 1) ssum += __shfl_xor_sync(0xffffffffu, ssum, o);
        float rinv = 1.0f / ssum;
        sc[q * 56 + lane] = e0 * rinv;
        if (lane + 32 < NNODE) sc[q * 56 + lane + 32] = e1 * rinv;
    }
    __syncthreads();

    {
        int q = tid >> 5, d = tid & 31;
        float o = 0.0f;
#pragma unroll 5
        for (int j = 0; j < NNODE; j++) o = fmaf(sc[q * 56 + j], KV[j * 68 + 32 + d], o);
        ao[tid] = o;
    }
    __syncthreads();

    {
        int q = tid >> 5, d = tid & 31;
        float o = bo[d];
#pragma unroll 8
        for (int k = 0; k < 32; k++) o = fmaf(ao[q * 32 + k], wo[k * 32 + d], o);
        s192[tid] = selu_f(o);
    }
    __syncthreads();

    {
        int q = tid >> 5, lane = tid & 31;
        float o = 0.0f;
#pragma unroll
        for (int i = lane; i < 192; i += 32) o = fmaf(s192[i], wfc[i * MQ + q], o);
#pragma unroll
        for (int off = 16; off > 0; off >>= 1) o += __shfl_xor_sync(0xffffffffu, o, off);
        if (lane == 0) out[(size_t)g * MQ + q] = o + bfc[q];
    }
}

// ---------------- host ----------------
extern "C" void kernel_launch(void* const* d_in, const int* in_sizes, int n_in,
                              void* d_out, int out_size) {
    const float* x    = (const float*)d_in[0];
    const int*   ei   = (const int*)d_in[1];
    const int*   shf  = (const int*)d_in[2];
    const float* wl0 = (const float*)d_in[3];
    const float* bl0 = (const float*)d_in[4];
    const float* wr0 = (const float*)d_in[5];
    const float* wl  = (const float*)d_in[6];
    const float* bl  = (const float*)d_in[7];
    const float* wr  = (const float*)d_in[8];
    const float* wq  = (const float*)d_in[9];
    const float* bq  = (const float*)d_in[10];
    const float* wk  = (const float*)d_in[11];
    const float* bk  = (const float*)d_in[12];
    const float* wv  = (const float*)d_in[13];
    const float* bv  = (const float*)d_in[14];
    const float* wo  = (const float*)d_in[15];
    const float* bo  = (const float*)d_in[16];
    const float* wfc = (const float*)d_in[17];
    const float* bfc = (const float*)d_in[18];
    float* out = (float*)d_out;

    // CSR build
    k_zero   <<<(NP1 + 255) / 256, 256>>>();
    k_count  <<<(NEDGE + 255) / 256, 256>>>(ei);
    k_scan1  <<<NB_SCAN, 1024>>>();
    k_scan2  <<<1, 1024>>>();
    k_scan3  <<<NB_SCAN, 1024>>>();
    k_reorder<<<(NEDGE + 255) / 256, 256>>>(ei);

    const int NBLK = NTOT / 128;   // 7040
    k_layer0<<<NBLK, 256>>>(x, wl0, bl0, wr0);
    for (int i = 0; i < 4; i++)
        k_layer<<<NBLK, 256>>>(i & 1, (i == 3) ? 1 : 0,
                               wl + i * HID * HID, bl + i * HID, wr + i * HID * HID);

    k_attn<<<BGR, 192>>>(x, shf, wq, bq, wk, bk, wv, bv, wo, bo, wfc, bfc, out);
}

// round 11
// speedup vs baseline: 2.7532x; 1.2308x over previous
#include <cuda_runtime.h>
#include <cuda_fp16.h>
#include <math.h>

// Problem constants
#define BGR   16384
#define NNODE 55
#define NTOT  (BGR * NNODE)        // 901120
#define INCH  13
#define HID   32
#define MQ    6
#define NEDGE (4 * NTOT)           // 3604480
#define NP1   (NTOT + 1)           // 901121
#define NB_SCAN ((NP1 + 1023) / 1024)  // 881

// ---------------- device scratch (no allocations allowed) ----------------
__device__ int   g_cnt[NP1];
__device__ int   g_rowptr[NP1];
__device__ int   g_cursor[NTOT];
__device__ int   g_bsum[1024];
__device__ int   g_srcs[NEDGE];
__device__ __align__(16) __half g_hA[(size_t)NTOT * HID];   // fp16 storage, fp32 compute
__device__ __align__(16) __half g_hB[(size_t)NTOT * HID];
__device__ __align__(16) float  g_jk[(size_t)NTOT * HID];   // fp32 (feeds attention)

__device__ __forceinline__ float selu_f(float v) {
    const float sc = 1.0507009873554804934193349852946f;
    const float al = 1.6732632423543772848170429916717f;
    return v > 0.0f ? sc * v : sc * al * expm1f(v);
}

// ---------------- CSR build ----------------
__global__ void k_zero() {
    int i = blockIdx.x * blockDim.x + threadIdx.x;
    if (i < NP1) g_cnt[i] = 0;
}

__global__ void k_count(const int* __restrict__ ei) {
    int i = blockIdx.x * blockDim.x + threadIdx.x;
    if (i < NEDGE) {
        unsigned d = (unsigned)ei[NEDGE + i];
        if (d < NTOT) atomicAdd(&g_cnt[d], 1);
    }
}

__global__ void k_scan1() {
    __shared__ int s[1024];
    int t = threadIdx.x;
    int i = blockIdx.x * 1024 + t;
    int v = (i < NP1) ? g_cnt[i] : 0;
    s[t] = v;
    for (int off = 1; off < 1024; off <<= 1) {
        __syncthreads();
        int xx = (t >= off) ? s[t - off] : 0;
        __syncthreads();
        s[t] += xx;
    }
    __syncthreads();
    int excl = (t == 0) ? 0 : s[t - 1];
    if (i < NP1) g_rowptr[i] = excl;
    if (t == 1023) g_bsum[blockIdx.x] = s[1023];
}

__global__ void k_scan2() {
    __shared__ int s[1024];
    int t = threadIdx.x;
    int v = (t < NB_SCAN) ? g_bsum[t] : 0;
    s[t] = v;
    for (int off = 1; off < 1024; off <<= 1) {
        __syncthreads();
        int xx = (t >= off) ? s[t - off] : 0;
        __syncthreads();
        s[t] += xx;
    }
    __syncthreads();
    int excl = (t == 0) ? 0 : s[t - 1];
    g_bsum[t] = excl;
}

__global__ void k_scan3() {
    int t = threadIdx.x;
    int i = blockIdx.x * 1024 + t;
    if (i < NP1) {
        int v = g_rowptr[i] + g_bsum[blockIdx.x];
        g_rowptr[i] = v;
        if (i < NTOT) g_cursor[i] = v;
    }
}

__global__ void k_reorder(const int* __restrict__ ei) {
    int i = blockIdx.x * blockDim.x + threadIdx.x;
    if (i < NEDGE) {
        unsigned s = (unsigned)ei[i];
        unsigned d = (unsigned)ei[NEDGE + i];
        if (d < NTOT && s < NTOT) {
            int pos = atomicAdd(&g_cursor[d], 1);
            g_srcs[pos] = (int)s;
        }
    }
}

// pack 16 fp32 (after selu) into 16 fp16 and store as 2x uint4 (32B)
__device__ __forceinline__ void store_half16(__half* hp, const float* sv) {
    __half2 t[8];
#pragma unroll
    for (int u = 0; u < 8; u++)
        t[u] = __float22half2_rn(make_float2(sv[2 * u], sv[2 * u + 1]));
    uint4 a, b;
    a.x = *(unsigned*)&t[0]; a.y = *(unsigned*)&t[1];
    a.z = *(unsigned*)&t[2]; a.w = *(unsigned*)&t[3];
    b.x = *(unsigned*)&t[4]; b.y = *(unsigned*)&t[5];
    b.z = *(unsigned*)&t[6]; b.w = *(unsigned*)&t[7];
    ((uint4*)hp)[0] = a;
    ((uint4*)hp)[1] = b;
}

// ---------------- SAGE layer 0 (13 -> 32), 128 nodes/block, scalar ----------------
__global__ void __launch_bounds__(256) k_layer0(
    const float* __restrict__ x,
    const float* __restrict__ wl0, const float* __restrict__ bl0,
    const float* __restrict__ wr0)
{
    __shared__ __align__(16) float W0[26 * 32];
    __shared__ __align__(16) float bias[32];
    __shared__ __align__(16) float Z[128 * 27];

    int tid = threadIdx.x;
    int base = blockIdx.x * 128;

    for (int i = tid; i < 26 * 32; i += 256)
        W0[i] = (i < 13 * 32) ? wl0[i] : wr0[i - 13 * 32];
    if (tid < 32) bias[tid] = bl0[tid];

    int lane = tid & 31, wp = tid >> 5;
    int hw = lane >> 4, ln = lane & 15;
    for (int it = 0; it < 8; it++) {
        int n = wp * 16 + it * 2 + hw;
        int node = base + n;
        int s = g_rowptr[node], e = g_rowptr[node + 1];
        float a = 0.0f;
#pragma unroll 4
        for (int j = s; j < e; j++) {
            int sr = g_srcs[j];
            if (ln < INCH) a += x[(size_t)sr * INCH + ln];
        }
        float inv = (e > s) ? 1.0f / (float)(e - s) : 0.0f;
        a *= inv;
        if (ln < INCH) {
            Z[n * 27 + ln] = a;
            Z[n * 27 + INCH + ln] = x[(size_t)node * INCH + ln];
        }
    }
    __syncthreads();

    int n = tid >> 1, half = tid & 1, cb = half * 16;
    float acc[16];
#pragma unroll
    for (int c = 0; c < 16; c++) acc[c] = bias[cb + c];
    const float* zr = &Z[n * 27];
#pragma unroll 2
    for (int k = 0; k < 26; k++) {
        float zk = zr[k];
        const float4* w4 = (const float4*)&W0[k * 32 + cb];
#pragma unroll
        for (int u = 0; u < 4; u++) {
            float4 w = w4[u];
            acc[u * 4 + 0] = fmaf(zk, w.x, acc[u * 4 + 0]);
            acc[u * 4 + 1] = fmaf(zk, w.y, acc[u * 4 + 1]);
            acc[u * 4 + 2] = fmaf(zk, w.z, acc[u * 4 + 2]);
            acc[u * 4 + 3] = fmaf(zk, w.w, acc[u * 4 + 3]);
        }
    }
    int node = base + n;
    float sv[16];
#pragma unroll
    for (int c = 0; c < 16; c++) sv[c] = selu_f(acc[c]);
    float4* jk4 = (float4*)g_jk;
    size_t rb = (size_t)node * 8 + half * 4;
#pragma unroll
    for (int u = 0; u < 4; u++)
        jk4[rb + u] = make_float4(sv[u * 4], sv[u * 4 + 1], sv[u * 4 + 2], sv[u * 4 + 3]);
    store_half16(g_hA + (size_t)node * 32 + cb, sv);
}

// ---------------- SAGE layers 1..4 (32 -> 32): gather + HMMA epilogue ----------------
// Z (fp16, stride 72 halves): cols 0..31 = mean-agg, 32..63 = self
// Wt (fp16, n-major, stride 68): Wt[n][k], k<32 -> wl, k>=32 -> wr
// P = Z @ W: M=128, N=32, K=64 via mma.m16n8k16, 8 warps x (m16, 4 n-tiles, 4 k-steps)
#define ZS 72
#define WS 68
__global__ void __launch_bounds__(256) k_layer(
    int dir, int last,
    const float* __restrict__ wlp, const float* __restrict__ blp,
    const float* __restrict__ wrp)
{
    const __half* __restrict__ hin = dir ? g_hB : g_hA;
    __half* __restrict__ hout = dir ? g_hA : g_hB;

    __shared__ __align__(16) __half Zh[128 * ZS];   // 18432 B
    __shared__ __align__(16) __half Wt[32 * WS];    // 4352 B
    __shared__ __align__(16) float bias_s[32];

    int tid = threadIdx.x;
    int base = blockIdx.x * 128;

    // stage transposed weights: Wt[n][k]
    for (int i = tid; i < 32 * 64; i += 256) {
        int n = i >> 6, k = i & 63;
        float w = (k < 32) ? wlp[k * 32 + n] : wrp[(k - 32) * 32 + n];
        Wt[n * WS + k] = __float2half(w);
    }
    if (tid < 32) bias_s[tid] = blp[tid];

    const uint2* __restrict__ hu = (const uint2*)hin;  // 1 uint2 = 4 halves

    // self rows -> Z cols 32..63 (raw fp16 copy)
    for (int idx = tid; idx < 128 * 8; idx += 256) {
        uint2 v = hu[(size_t)base * 8 + idx];
        int n = idx >> 3, ch = idx & 7;
        *(uint2*)&Zh[n * ZS + 32 + ch * 4] = v;
    }

    // gather: quarter-warp per node (8 lanes x 8B = 64B row), 4 chains/warp
    int lane = tid & 31, wp = tid >> 5;
    int q = lane >> 3, li = lane & 7;
    for (int it = 0; it < 4; it++) {
        int n = wp * 16 + it * 4 + q;
        int node = base + n;
        int s = g_rowptr[node], e = g_rowptr[node + 1];
        float4 acc = make_float4(0.f, 0.f, 0.f, 0.f);
#pragma unroll 4
        for (int j = s; j < e; j++) {
            int sr = g_srcs[j];
            uint2 v = hu[(size_t)sr * 8 + li];
            __half2 h0 = *(__half2*)&v.x;
            __half2 h1 = *(__half2*)&v.y;
            float2 f0 = __half22float2(h0), f1 = __half22float2(h1);
            acc.x += f0.x; acc.y += f0.y; acc.z += f1.x; acc.w += f1.y;
        }
        float inv = (e > s) ? 1.0f / (float)(e - s) : 0.0f;
        __half2 p0 = __float22half2_rn(make_float2(acc.x * inv, acc.y * inv));
        __half2 p1 = __float22half2_rn(make_float2(acc.z * inv, acc.w * inv));
        uint2 st;
        st.x = *(unsigned*)&p0;
        st.y = *(unsigned*)&p1;
        *(uint2*)&Zh[n * ZS + li * 4] = st;
    }
    __syncthreads();

    // ---- tensor-core epilogue ----
    int warp = tid >> 5;
    int m0 = warp * 16;
    int col0 = (lane & 3) * 2;          // D col pair base within n-tile
    int rrow = lane >> 2;               // D row within m16 (and +8)

    float cc[4][4];
#pragma unroll
    for (int nt = 0; nt < 4; nt++) {
        float b0 = bias_s[nt * 8 + col0];
        float b1 = bias_s[nt * 8 + col0 + 1];
        cc[nt][0] = b0; cc[nt][1] = b1; cc[nt][2] = b0; cc[nt][3] = b1;
    }

    // A (ldmatrix) lane addressing
    int arow = m0 + ((lane >> 3) & 1) * 8 + (lane & 7);
    int acolbase = (lane >> 4) * 8;
    const __half* aptr = &Zh[arow * ZS];
    // B lane addressing: b0 = {W[k0][n], W[k0+1][n]}, k0=(lane&3)*2, n=lane>>2
    const __half* bptr = &Wt[(lane >> 2) * WS + col0];

#pragma unroll
    for (int ko = 0; ko < 4; ko++) {
        unsigned a0, a1, a2, a3;
        unsigned aaddr = (unsigned)__cvta_generic_to_shared(aptr + ko * 16 + acolbase);
        asm volatile("ldmatrix.sync.aligned.m8n8.x4.shared.b16 {%0,%1,%2,%3}, [%4];\n"
                     : "=r"(a0), "=r"(a1), "=r"(a2), "=r"(a3) : "r"(aaddr));
#pragma unroll
        for (int nt = 0; nt < 4; nt++) {
            unsigned b0 = *(const unsigned*)(bptr + nt * 8 * WS + ko * 16);
            unsigned b1 = *(const unsigned*)(bptr + nt * 8 * WS + ko * 16 + 8);
            asm volatile(
                "mma.sync.aligned.m16n8k16.row.col.f32.f16.f16.f32 "
                "{%0,%1,%2,%3}, {%4,%5,%6,%7}, {%8,%9}, {%0,%1,%2,%3};\n"
                : "+f"(cc[nt][0]), "+f"(cc[nt][1]), "+f"(cc[nt][2]), "+f"(cc[nt][3])
                : "r"(a0), "r"(a1), "r"(a2), "r"(a3), "r"(b0), "r"(b1));
        }
    }

    // selu + jk max (fp32) + hout (fp16)
    int rbase = base + m0 + rrow;
#pragma unroll
    for (int rr = 0; rr < 2; rr++) {
        int node = rbase + rr * 8;
        float* jrow = &g_jk[(size_t)node * 32];
        __half* hrow = hout + (size_t)node * 32;
#pragma unroll
        for (int nt = 0; nt < 4; nt++) {
            int c = nt * 8 + col0;
            float v0 = selu_f(cc[nt][rr * 2 + 0]);
            float v1 = selu_f(cc[nt][rr * 2 + 1]);
            float2 jv = *(float2*)&jrow[c];
            jv.x = fmaxf(jv.x, v0);
            jv.y = fmaxf(jv.y, v1);
            *(float2*)&jrow[c] = jv;
            if (!last) *(__half2*)&hrow[c] = __float22half2_rn(make_float2(v0, v1));
        }
    }
}

// ---------------- per-graph attention + FC (192 threads = 6 warps) ----------------
__global__ void __launch_bounds__(192) k_attn(
    const float* __restrict__ x,
    const int* __restrict__ shuf,
    const float* __restrict__ wq, const float* __restrict__ bq,
    const float* __restrict__ wk, const float* __restrict__ bk,
    const float* __restrict__ wv, const float* __restrict__ bv,
    const float* __restrict__ wo, const float* __restrict__ bo,
    const float* __restrict__ wfc, const float* __restrict__ bfc,
    float* __restrict__ out)
{
    __shared__ __align__(16) float keys[NNODE * 33];
    __shared__ __align__(16) float KV[NNODE * 68];
    __shared__ __align__(16) float Wkv[32 * 64];
    __shared__ __align__(16) float bkv[64];
    __shared__ __align__(16) float Qs[MQ * 32];
    __shared__ __align__(16) float sc[MQ * 56];
    __shared__ __align__(16) float ao[MQ * 32];
    __shared__ __align__(16) float s192[192];
    __shared__ unsigned mbits[2];
    __shared__ int qidx[MQ];

    int g = blockIdx.x;
    int tid = threadIdx.x;
    int nbase = g * NNODE;

    for (int idx = tid; idx < NNODE * 32; idx += 192) {
        int j = idx >> 5, c = idx & 31;
        keys[j * 33 + c] = selu_f(g_jk[(size_t)nbase * 32 + idx]);
    }
    for (int i = tid; i < 2048; i += 192) {
        int k = i >> 6, c = i & 63;
        Wkv[i] = (c < 32) ? wk[k * 32 + c] : wv[k * 32 + (c - 32)];
    }
    if (tid < 64) bkv[tid] = (tid < 32) ? bk[tid] : bv[tid - 32];

    if (tid < 64) {
        bool on = (tid < NNODE) ? (x[(size_t)(nbase + tid) * INCH + (INCH - 3)] > 0.5f) : false;
        unsigned b = __ballot_sync(0xffffffffu, on);
        if ((tid & 31) == 0) mbits[tid >> 5] = b;
    }
    __syncthreads();

    if (tid < MQ) {
        int si = shuf[(size_t)g * MQ + tid];
        si = si < 0 ? 0 : (si > MQ - 1 ? MQ - 1 : si);
        unsigned m0 = mbits[0], m1 = mbits[1];
        int c0 = __popc(m0);
        int nth = si, pos = 0;
        unsigned m = m0; int off = 0;
        if (nth >= c0) { nth -= c0; m = m1; off = 32; }
        for (int b = 0; b < 32; b++) {
            if ((m >> b) & 1u) { if (nth == 0) { pos = off + b; break; } nth--; }
        }
        qidx[tid] = pos;
    }
    __syncthreads();

    {
        int q = tid >> 5, c = tid & 31;
        const float* kr = &keys[qidx[q] * 33];
        float o = bq[c];
#pragma unroll 8
        for (int k = 0; k < 32; k++) o = fmaf(kr[k], wq[k * 32 + c], o);
        Qs[tid] = o;
    }

    for (int idx = tid; idx < NNODE * 8; idx += 192) {
        int j = idx >> 3, og = idx & 7, cb = og * 8;
        float a[8];
#pragma unroll
        for (int u = 0; u < 8; u++) a[u] = bkv[cb + u];
        const float* zr = &keys[j * 33];
#pragma unroll 8
        for (int k = 0; k < 32; k++) {
            float zk = zr[k];
            float4 w0 = *(const float4*)&Wkv[k * 64 + cb];
            float4 w1 = *(const float4*)&Wkv[k * 64 + cb + 4];
            a[0] = fmaf(zk, w0.x, a[0]); a[1] = fmaf(zk, w0.y, a[1]);
            a[2] = fmaf(zk, w0.z, a[2]); a[3] = fmaf(zk, w0.w, a[3]);
            a[4] = fmaf(zk, w1.x, a[4]); a[5] = fmaf(zk, w1.y, a[5]);
            a[6] = fmaf(zk, w1.z, a[6]); a[7] = fmaf(zk, w1.w, a[7]);
        }
        *(float4*)&KV[j * 68 + cb] = make_float4(a[0], a[1], a[2], a[3]);
        *(float4*)&KV[j * 68 + cb + 4] = make_float4(a[4], a[5], a[6], a[7]);
    }
    __syncthreads();

    const float scale = 0.17677669529663687f;
    for (int idx = tid; idx < MQ * NNODE; idx += 192) {
        int q = idx / NNODE, j = idx - q * NNODE;
        float o = 0.0f;
#pragma unroll 8
        for (int k = 0; k < 32; k++) o = fmaf(Qs[q * 32 + k], KV[j * 68 + k], o);
        sc[q * 56 + j] = o * scale;
    }
    __syncthreads();

    {
        int q = tid >> 5, lane = tid & 31;
        float v0 = sc[q * 56 + lane];
        float v1 = (lane + 32 < NNODE) ? sc[q * 56 + lane + 32] : -1e30f;
        float m = fmaxf(v0, v1);
#pragma unroll
        for (int o = 16; o > 0; o >>= 1) m = fmaxf(m, __shfl_xor_sync(0xffffffffu, m, o));
        float e0 = expf(v0 - m);
        float e1 = (lane + 32 < NNODE) ? expf(v1 - m) : 0.0f;
        float ssum = e0 + e1;
#pragma unroll
        for (int o = 16; o > 0; o >>= 1) ssum += __shfl_xor_sync(0xffffffffu, ssum, o);
        float rinv = 1.0f / ssum;
        sc[q * 56 + lane] = e0 * rinv;
        if (lane + 32 < NNODE) sc[q * 56 + lane + 32] = e1 * rinv;
    }
    __syncthreads();

    {
        int q = tid >> 5, d = tid & 31;
        float o = 0.0f;
#pragma unroll 5
        for (int j = 0; j < NNODE; j++) o = fmaf(sc[q * 56 + j], KV[j * 68 + 32 + d], o);
        ao[tid] = o;
    }
    __syncthreads();

    {
        int q = tid >> 5, d = tid & 31;
        float o = bo[d];
#pragma unroll 8
        for (int k = 0; k < 32; k++) o = fmaf(ao[q * 32 + k], wo[k * 32 + d], o);
        s192[tid] = selu_f(o);
    }
    __syncthreads();

    {
        int q = tid >> 5, lane = tid & 31;
        float o = 0.0f;
#pragma unroll
        for (int i = lane; i < 192; i += 32) o = fmaf(s192[i], wfc[i * MQ + q], o);
#pragma unroll
        for (int off = 16; off > 0; off >>= 1) o += __shfl_xor_sync(0xffffffffu, o, off);
        if (lane == 0) out[(size_t)g * MQ + q] = o + bfc[q];
    }
}

// ---------------- host ----------------
extern "C" void kernel_launch(void* const* d_in, const int* in_sizes, int n_in,
                              void* d_out, int out_size) {
    const float* x    = (const float*)d_in[0];
    const int*   ei   = (const int*)d_in[1];
    const int*   shf  = (const int*)d_in[2];
    const float* wl0 = (const float*)d_in[3];
    const float* bl0 = (const float*)d_in[4];
    const float* wr0 = (const float*)d_in[5];
    const float* wl  = (const float*)d_in[6];
    const float* bl  = (const float*)d_in[7];
    const float* wr  = (const float*)d_in[8];
    const float* wq  = (const float*)d_in[9];
    const float* bq  = (const float*)d_in[10];
    const float* wk  = (const float*)d_in[11];
    const float* bk  = (const float*)d_in[12];
    const float* wv  = (const float*)d_in[13];
    const float* bv  = (const float*)d_in[14];
    const float* wo  = (const float*)d_in[15];
    const float* bo  = (const float*)d_in[16];
    const float* wfc = (const float*)d_in[17];
    const float* bfc = (const float*)d_in[18];
    float* out = (float*)d_out;

    // CSR build
    k_zero   <<<(NP1 + 255) / 256, 256>>>();
    k_count  <<<(NEDGE + 255) / 256, 256>>>(ei);
    k_scan1  <<<NB_SCAN, 1024>>>();
    k_scan2  <<<1, 1024>>>();
    k_scan3  <<<NB_SCAN, 1024>>>();
    k_reorder<<<(NEDGE + 255) / 256, 256>>>(ei);

    const int NBLK = NTOT / 128;   // 7040
    k_layer0<<<NBLK, 256>>>(x, wl0, bl0, wr0);
    for (int i = 0; i < 4; i++)
        k_layer<<<NBLK, 256>>>(i & 1, (i == 3) ? 1 : 0,
                               wl + i * HID * HID, bl + i * HID, wr + i * HID * HID);

    k_attn<<<BGR, 192>>>(x, shf, wq, bq, wk, bk, wv, bv, wo, bo, wfc, bfc, out);
}

// round 14
// speedup vs baseline: 2.9242x; 1.0621x over previous
#include <cuda_runtime.h>
#include <cuda_fp16.h>
#include <math.h>

// Problem constants
#define BGR   16384
#define NNODE 55
#define NTOT  (BGR * NNODE)        // 901120
#define INCH  13
#define HID   32
#define MQ    6
#define NEDGE (4 * NTOT)           // 3604480
#define NP1   (NTOT + 1)           // 901121
#define NB_SCAN ((NP1 + 1023) / 1024)  // 881

// ---------------- device scratch (no allocations allowed) ----------------
__device__ int   g_cnt[NP1];
__device__ int   g_rowptr[NP1];
__device__ int   g_cursor[NTOT];
__device__ int   g_bsum[1024];
__device__ int   g_srcs[NEDGE];
__device__ __align__(16) __half g_hA[(size_t)NTOT * HID];   // fp16 storage, fp32 compute
__device__ __align__(16) __half g_hB[(size_t)NTOT * HID];
__device__ __align__(16) __half g_jk[(size_t)NTOT * HID];   // fp16 (max of fp16 h values)

__device__ __forceinline__ float selu_f(float v) {
    const float sc = 1.0507009873554804934193349852946f;
    const float al = 1.6732632423543772848170429916717f;
    return v > 0.0f ? sc * v : sc * al * expm1f(v);
}

// ---------------- CSR build ----------------
__global__ void k_zero() {
    int i = blockIdx.x * blockDim.x + threadIdx.x;
    if (i < NP1) g_cnt[i] = 0;
}

__global__ void k_count(const int* __restrict__ ei) {
    int i = blockIdx.x * blockDim.x + threadIdx.x;
    if (i < NEDGE) {
        unsigned d = (unsigned)ei[NEDGE + i];
        if (d < NTOT) atomicAdd(&g_cnt[d], 1);
    }
}

__global__ void k_scan1() {
    __shared__ int s[1024];
    int t = threadIdx.x;
    int i = blockIdx.x * 1024 + t;
    int v = (i < NP1) ? g_cnt[i] : 0;
    s[t] = v;
    for (int off = 1; off < 1024; off <<= 1) {
        __syncthreads();
        int xx = (t >= off) ? s[t - off] : 0;
        __syncthreads();
        s[t] += xx;
    }
    __syncthreads();
    int excl = (t == 0) ? 0 : s[t - 1];
    if (i < NP1) g_rowptr[i] = excl;
    if (t == 1023) g_bsum[blockIdx.x] = s[1023];
}

__global__ void k_scan2() {
    __shared__ int s[1024];
    int t = threadIdx.x;
    int v = (t < NB_SCAN) ? g_bsum[t] : 0;
    s[t] = v;
    for (int off = 1; off < 1024; off <<= 1) {
        __syncthreads();
        int xx = (t >= off) ? s[t - off] : 0;
        __syncthreads();
        s[t] += xx;
    }
    __syncthreads();
    int excl = (t == 0) ? 0 : s[t - 1];
    g_bsum[t] = excl;
}

__global__ void k_scan3() {
    int t = threadIdx.x;
    int i = blockIdx.x * 1024 + t;
    if (i < NP1) {
        int v = g_rowptr[i] + g_bsum[blockIdx.x];
        g_rowptr[i] = v;
        if (i < NTOT) g_cursor[i] = v;
    }
}

__global__ void k_reorder(const int* __restrict__ ei) {
    int i = blockIdx.x * blockDim.x + threadIdx.x;
    if (i < NEDGE) {
        unsigned s = (unsigned)ei[i];
        unsigned d = (unsigned)ei[NEDGE + i];
        if (d < NTOT && s < NTOT) {
            int pos = atomicAdd(&g_cursor[d], 1);
            g_srcs[pos] = (int)s;
        }
    }
}

// pack 16 fp32 (after selu) into 16 fp16 and store as 2x uint4 (32B)
__device__ __forceinline__ void store_half16(__half* hp, const float* sv) {
    __half2 t[8];
#pragma unroll
    for (int u = 0; u < 8; u++)
        t[u] = __float22half2_rn(make_float2(sv[2 * u], sv[2 * u + 1]));
    uint4 a, b;
    a.x = *(unsigned*)&t[0]; a.y = *(unsigned*)&t[1];
    a.z = *(unsigned*)&t[2]; a.w = *(unsigned*)&t[3];
    b.x = *(unsigned*)&t[4]; b.y = *(unsigned*)&t[5];
    b.z = *(unsigned*)&t[6]; b.w = *(unsigned*)&t[7];
    ((uint4*)hp)[0] = a;
    ((uint4*)hp)[1] = b;
}

// ---------------- SAGE layer 0 (13 -> 32), 128 nodes/block, scalar ----------------
__global__ void __launch_bounds__(256) k_layer0(
    const float* __restrict__ x,
    const float* __restrict__ wl0, const float* __restrict__ bl0,
    const float* __restrict__ wr0)
{
    __shared__ __align__(16) float W0[26 * 32];
    __shared__ __align__(16) float bias[32];
    __shared__ __align__(16) float Z[128 * 27];

    int tid = threadIdx.x;
    int base = blockIdx.x * 128;

    for (int i = tid; i < 26 * 32; i += 256)
        W0[i] = (i < 13 * 32) ? wl0[i] : wr0[i - 13 * 32];
    if (tid < 32) bias[tid] = bl0[tid];

    int lane = tid & 31, wp = tid >> 5;
    int hw = lane >> 4, ln = lane & 15;
    for (int it = 0; it < 8; it++) {
        int n = wp * 16 + it * 2 + hw;
        int node = base + n;
        int s = g_rowptr[node], e = g_rowptr[node + 1];
        float a = 0.0f;
#pragma unroll 4
        for (int j = s; j < e; j++) {
            int sr = g_srcs[j];
            if (ln < INCH) a += x[(size_t)sr * INCH + ln];
        }
        float inv = (e > s) ? 1.0f / (float)(e - s) : 0.0f;
        a *= inv;
        if (ln < INCH) {
            Z[n * 27 + ln] = a;
            Z[n * 27 + INCH + ln] = x[(size_t)node * INCH + ln];
        }
    }
    __syncthreads();

    int n = tid >> 1, half = tid & 1, cb = half * 16;
    float acc[16];
#pragma unroll
    for (int c = 0; c < 16; c++) acc[c] = bias[cb + c];
    const float* zr = &Z[n * 27];
#pragma unroll 2
    for (int k = 0; k < 26; k++) {
        float zk = zr[k];
        const float4* w4 = (const float4*)&W0[k * 32 + cb];
#pragma unroll
        for (int u = 0; u < 4; u++) {
            float4 w = w4[u];
            acc[u * 4 + 0] = fmaf(zk, w.x, acc[u * 4 + 0]);
            acc[u * 4 + 1] = fmaf(zk, w.y, acc[u * 4 + 1]);
            acc[u * 4 + 2] = fmaf(zk, w.z, acc[u * 4 + 2]);
            acc[u * 4 + 3] = fmaf(zk, w.w, acc[u * 4 + 3]);
        }
    }
    int node = base + n;
    float sv[16];
#pragma unroll
    for (int c = 0; c < 16; c++) sv[c] = selu_f(acc[c]);
    store_half16(g_hA + (size_t)node * 32 + cb, sv);
    store_half16(g_jk + (size_t)node * 32 + cb, sv);
}

// ---------------- SAGE layers 1..4 (32 -> 32): gather + HMMA epilogue ----------------
// Z (fp16, stride 72 halves): cols 0..31 = mean-agg, 32..63 = self
// Wt (fp16, n-major, stride 68): Wt[n][k], k<32 -> wl, k>=32 -> wr
// P = Z @ W: M=128, N=32, K=64 via mma.m16n8k16, 8 warps x (m16, 4 n-tiles, 4 k-steps)
#define ZS 72
#define WS 68
__global__ void __launch_bounds__(256) k_layer(
    int dir, int last,
    const float* __restrict__ wlp, const float* __restrict__ blp,
    const float* __restrict__ wrp)
{
    const __half* __restrict__ hin = dir ? g_hB : g_hA;
    __half* __restrict__ hout = dir ? g_hA : g_hB;

    __shared__ __align__(16) __half Zh[128 * ZS];   // 18432 B
    __shared__ __align__(16) __half Wt[32 * WS];    // 4352 B
    __shared__ __align__(16) float bias_s[32];

    int tid = threadIdx.x;
    int base = blockIdx.x * 128;

    // stage transposed weights: Wt[n][k]
    for (int i = tid; i < 32 * 64; i += 256) {
        int n = i >> 6, k = i & 63;
        float w = (k < 32) ? wlp[k * 32 + n] : wrp[(k - 32) * 32 + n];
        Wt[n * WS + k] = __float2half(w);
    }
    if (tid < 32) bias_s[tid] = blp[tid];

    const uint2* __restrict__ hu = (const uint2*)hin;  // 1 uint2 = 4 halves

    // self rows -> Z cols 32..63 (raw fp16 copy)
    for (int idx = tid; idx < 128 * 8; idx += 256) {
        uint2 v = hu[(size_t)base * 8 + idx];
        int n = idx >> 3, ch = idx & 7;
        *(uint2*)&Zh[n * ZS + 32 + ch * 4] = v;
    }

    // gather: quarter-warp per node (8 lanes x 8B = 64B row), 4 chains/warp
    int lane = tid & 31, wp = tid >> 5;
    int q = lane >> 3, li = lane & 7;
    for (int it = 0; it < 4; it++) {
        int n = wp * 16 + it * 4 + q;
        int node = base + n;
        int s = g_rowptr[node], e = g_rowptr[node + 1];
        float4 acc = make_float4(0.f, 0.f, 0.f, 0.f);
#pragma unroll 4
        for (int j = s; j < e; j++) {
            int sr = g_srcs[j];
            uint2 v = hu[(size_t)sr * 8 + li];
            __half2 h0 = *(__half2*)&v.x;
            __half2 h1 = *(__half2*)&v.y;
            float2 f0 = __half22float2(h0), f1 = __half22float2(h1);
            acc.x += f0.x; acc.y += f0.y; acc.z += f1.x; acc.w += f1.y;
        }
        float inv = (e > s) ? 1.0f / (float)(e - s) : 0.0f;
        __half2 p0 = __float22half2_rn(make_float2(acc.x * inv, acc.y * inv));
        __half2 p1 = __float22half2_rn(make_float2(acc.z * inv, acc.w * inv));
        uint2 st;
        st.x = *(unsigned*)&p0;
        st.y = *(unsigned*)&p1;
        *(uint2*)&Zh[n * ZS + li * 4] = st;
    }
    __syncthreads();

    // ---- tensor-core epilogue ----
    int warp = tid >> 5;
    int m0 = warp * 16;
    int col0 = (lane & 3) * 2;          // D col pair base within n-tile
    int rrow = lane >> 2;               // D row within m16 (and +8)

    float cc[4][4];
#pragma unroll
    for (int nt = 0; nt < 4; nt++) {
        float b0 = bias_s[nt * 8 + col0];
        float b1 = bias_s[nt * 8 + col0 + 1];
        cc[nt][0] = b0; cc[nt][1] = b1; cc[nt][2] = b0; cc[nt][3] = b1;
    }

    // A (ldmatrix) lane addressing
    int arow = m0 + ((lane >> 3) & 1) * 8 + (lane & 7);
    int acolbase = (lane >> 4) * 8;
    const __half* aptr = &Zh[arow * ZS];
    // B lane addressing: b0 = {W[k0][n], W[k0+1][n]}, k0=(lane&3)*2, n=lane>>2
    const __half* bptr = &Wt[(lane >> 2) * WS + col0];

#pragma unroll
    for (int ko = 0; ko < 4; ko++) {
        unsigned a0, a1, a2, a3;
        unsigned aaddr = (unsigned)__cvta_generic_to_shared(aptr + ko * 16 + acolbase);
        asm volatile("ldmatrix.sync.aligned.m8n8.x4.shared.b16 {%0,%1,%2,%3}, [%4];\n"
                     : "=r"(a0), "=r"(a1), "=r"(a2), "=r"(a3) : "r"(aaddr));
#pragma unroll
        for (int nt = 0; nt < 4; nt++) {
            unsigned b0 = *(const unsigned*)(bptr + nt * 8 * WS + ko * 16);
            unsigned b1 = *(const unsigned*)(bptr + nt * 8 * WS + ko * 16 + 8);
            asm volatile(
                "mma.sync.aligned.m16n8k16.row.col.f32.f16.f16.f32 "
                "{%0,%1,%2,%3}, {%4,%5,%6,%7}, {%8,%9}, {%0,%1,%2,%3};\n"
                : "+f"(cc[nt][0]), "+f"(cc[nt][1]), "+f"(cc[nt][2]), "+f"(cc[nt][3])
                : "r"(a0), "r"(a1), "r"(a2), "r"(a3), "r"(b0), "r"(b1));
        }
    }

    // selu + jk max (fp16 RMW) + hout (fp16)
    int rbase = base + m0 + rrow;
#pragma unroll
    for (int rr = 0; rr < 2; rr++) {
        int node = rbase + rr * 8;
        __half* jrow = g_jk + (size_t)node * 32;
        __half* hrow = hout + (size_t)node * 32;
#pragma unroll
        for (int nt = 0; nt < 4; nt++) {
            int c = nt * 8 + col0;
            float v0 = selu_f(cc[nt][rr * 2 + 0]);
            float v1 = selu_f(cc[nt][rr * 2 + 1]);
            __half2 nv = __float22half2_rn(make_float2(v0, v1));
            __half2 ov = *(__half2*)&jrow[c];
            *(__half2*)&jrow[c] = __hmax2(ov, nv);
            if (!last) *(__half2*)&hrow[c] = nv;
        }
    }
}

// ---------------- per-graph attention + FC (192 threads = 6 warps) ----------------
__global__ void __launch_bounds__(192) k_attn(
    const float* __restrict__ x,
    const int* __restrict__ shuf,
    const float* __restrict__ wq, const float* __restrict__ bq,
    const float* __restrict__ wk, const float* __restrict__ bk,
    const float* __restrict__ wv, const float* __restrict__ bv,
    const float* __restrict__ wo, const float* __restrict__ bo,
    const float* __restrict__ wfc, const float* __restrict__ bfc,
    float* __restrict__ out)
{
    __shared__ __align__(16) float keys[NNODE * 33];
    __shared__ __align__(16) float KV[NNODE * 68];
    __shared__ __align__(16) float Wkv[32 * 64];
    __shared__ __align__(16) float bkv[64];
    __shared__ __align__(16) float Qs[MQ * 32];
    __shared__ __align__(16) float sc[MQ * 56];
    __shared__ __align__(16) float ao[MQ * 32];
    __shared__ __align__(16) float s192[192];
    __shared__ unsigned mbits[2];
    __shared__ int qidx[MQ];

    int g = blockIdx.x;
    int tid = threadIdx.x;
    int nbase = g * NNODE;

    // keys = selu(jk) — fp16 read, fp32 smem
    const __half2* jk2 = (const __half2*)(g_jk + (size_t)nbase * 32);
    for (int idx = tid; idx < NNODE * 16; idx += 192) {
        __half2 h = jk2[idx];
        float2 f = __half22float2(h);
        int j = idx >> 4, c2 = (idx & 15) << 1;
        keys[j * 33 + c2]     = selu_f(f.x);
        keys[j * 33 + c2 + 1] = selu_f(f.y);
    }
    for (int i = tid; i < 2048; i += 192) {
        int k = i >> 6, c = i & 63;
        Wkv[i] = (c < 32) ? wk[k * 32 + c] : wv[k * 32 + (c - 32)];
    }
    if (tid < 64) bkv[tid] = (tid < 32) ? bk[tid] : bv[tid - 32];

    if (tid < 64) {
        bool on = (tid < NNODE) ? (x[(size_t)(nbase + tid) * INCH + (INCH - 3)] > 0.5f) : false;
        unsigned b = __ballot_sync(0xffffffffu, on);
        if ((tid & 31) == 0) mbits[tid >> 5] = b;
    }
    __syncthreads();

    if (tid < MQ) {
        int si = shuf[(size_t)g * MQ + tid];
        si = si < 0 ? 0 : (si > MQ - 1 ? MQ - 1 : si);
        unsigned m0 = mbits[0], m1 = mbits[1];
        int c0 = __popc(m0);
        int nth = si, pos = 0;
        unsigned m = m0; int off = 0;
        if (nth >= c0) { nth -= c0; m = m1; off = 32; }
        for (int b = 0; b < 32; b++) {
            if ((m >> b) & 1u) { if (nth == 0) { pos = off + b; break; } nth--; }
        }
        qidx[tid] = pos;
    }
    __syncthreads();

    {
        int q = tid >> 5, c = tid & 31;
        const float* kr = &keys[qidx[q] * 33];
        float o = bq[c];
#pragma unroll 8
        for (int k = 0; k < 32; k++) o = fmaf(kr[k], wq[k * 32 + c], o);
        Qs[tid] = o;
    }

    for (int idx = tid; idx < NNODE * 8; idx += 192) {
        int j = idx >> 3, og = idx & 7, cb = og * 8;
        float a[8];
#pragma unroll
        for (int u = 0; u < 8; u++) a[u] = bkv[cb + u];
        const float* zr = &keys[j * 33];
#pragma unroll 8
        for (int k = 0; k < 32; k++) {
            float zk = zr[k];
            float4 w0 = *(const float4*)&Wkv[k * 64 + cb];
            float4 w1 = *(const float4*)&Wkv[k * 64 + cb + 4];
            a[0] = fmaf(zk, w0.x, a[0]); a[1] = fmaf(zk, w0.y, a[1]);
            a[2] = fmaf(zk, w0.z, a[2]); a[3] = fmaf(zk, w0.w, a[3]);
            a[4] = fmaf(zk, w1.x, a[4]); a[5] = fmaf(zk, w1.y, a[5]);
            a[6] = fmaf(zk, w1.z, a[6]); a[7] = fmaf(zk, w1.w, a[7]);
        }
        *(float4*)&KV[j * 68 + cb] = make_float4(a[0], a[1], a[2], a[3]);
        *(float4*)&KV[j * 68 + cb + 4] = make_float4(a[4], a[5], a[6], a[7]);
    }
    __syncthreads();

    const float scale = 0.17677669529663687f;
    for (int idx = tid; idx < MQ * NNODE; idx += 192) {
        int q = idx / NNODE, j = idx - q * NNODE;
        float o = 0.0f;
#pragma unroll 8
        for (int k = 0; k < 32; k++) o = fmaf(Qs[q * 32 + k], KV[j * 68 + k], o);
        sc[q * 56 + j] = o * scale;
    }
    __syncthreads();

    {
        int q = tid >> 5, lane = tid & 31;
        float v0 = sc[q * 56 + lane];
        float v1 = (lane + 32 < NNODE) ? sc[q * 56 + lane + 32] : -1e30f;
        float m = fmaxf(v0, v1);
#pragma unroll
        for (int o = 16; o > 0; o >>= 1) m = fmaxf(m, __shfl_xor_sync(0xffffffffu, m, o));
        float e0 = expf(v0 - m);
        float e1 = (lane + 32 < NNODE) ? expf(v1 - m) : 0.0f;
        float ssum = e0 + e1;
#pragma unroll
        for (int o = 16; o > 0; o >>= 1) ssum += __shfl_xor_sync(0xffffffffu, ssum, o);
        float rinv = 1.0f / ssum;
        sc[q * 56 + lane] = e0 * rinv;
        if (lane + 32 < NNODE) sc[q * 56 + lane + 32] = e1 * rinv;
    }
    __syncthreads();

    {
        int q = tid >> 5, d = tid & 31;
        float o = 0.0f;
#pragma unroll 5
        for (int j = 0; j < NNODE; j++) o = fmaf(sc[q * 56 + j], KV[j * 68 + 32 + d], o);
        ao[tid] = o;
    }
    __syncthreads();

    {
        int q = tid >> 5, d = tid & 31;
        float o = bo[d];
#pragma unroll 8
        for (int k = 0; k < 32; k++) o = fmaf(ao[q * 32 + k], wo[k * 32 + d], o);
        s192[tid] = selu_f(o);
    }
    __syncthreads();

    {
        int q = tid >> 5, lane = tid & 31;
        float o = 0.0f;
#pragma unroll
        for (int i = lane; i < 192; i += 32) o = fmaf(s192[i], wfc[i * MQ + q], o);
#pragma unroll
        for (int off = 16; off > 0; off >>= 1) o += __shfl_xor_sync(0xffffffffu, o, off);
        if (lane == 0) out[(size_t)g * MQ + q] = o + bfc[q];
    }
}

// ---------------- host ----------------
extern "C" void kernel_launch(void* const* d_in, const int* in_sizes, int n_in,
                              void* d_out, int out_size) {
    const float* x    = (const float*)d_in[0];
    const int*   ei   = (const int*)d_in[1];
    const int*   shf  = (const int*)d_in[2];
    const float* wl0 = (const float*)d_in[3];
    const float* bl0 = (const float*)d_in[4];
    const float* wr0 = (const float*)d_in[5];
    const float* wl  = (const float*)d_in[6];
    const float* bl  = (const float*)d_in[7];
    const float* wr  = (const float*)d_in[8];
    const float* wq  = (const float*)d_in[9];
    const float* bq  = (const float*)d_in[10];
    const float* wk  = (const float*)d_in[11];
    const float* bk  = (const float*)d_in[12];
    const float* wv  = (const float*)d_in[13];
    const float* bv  = (const float*)d_in[14];
    const float* wo  = (const float*)d_in[15];
    const float* bo  = (const float*)d_in[16];
    const float* wfc = (const float*)d_in[17];
    const float* bfc = (const float*)d_in[18];
    float* out = (float*)d_out;

    // CSR build
    k_zero   <<<(NP1 + 255) / 256, 256>>>();
    k_count  <<<(NEDGE + 255) / 256, 256>>>(ei);
    k_scan1  <<<NB_SCAN, 1024>>>();
    k_scan2  <<<1, 1024>>>();
    k_scan3  <<<NB_SCAN, 1024>>>();
    k_reorder<<<(NEDGE + 255) / 256, 256>>>(ei);

    const int NBLK = NTOT / 128;   // 7040
    k_layer0<<<NBLK, 256>>>(x, wl0, bl0, wr0);
    for (int i = 0; i < 4; i++)
        k_layer<<<NBLK, 256>>>(i & 1, (i == 3) ? 1 : 0,
                               wl + i * HID * HID, bl + i * HID, wr + i * HID * HID);

    k_attn<<<BGR, 192>>>(x, shf, wq, bq, wk, bk, wv, bv, wo, bo, wfc, bfc, out);
}